// round 5
// baseline (speedup 1.0000x reference)
#include <cuda_runtime.h>
#include <math.h>

#define TILE_M   128
#define NTHREADS 256
#define HBUF     (TILE_M * 64)

// shared memory layout (float offsets)
#define SH_W      (6 * HBUF)          // 49152 : staged weight matrix (<=64x64)
#define SH_B      (SH_W + 64 * 64)    // 53248 : staged bias (64)
#define SH_WXYZR  (SH_B + 64)         // 53312 : Wx,Wy,Wz,Wr (4*64)
#define SH_XYZR   (SH_WXYZR + 256)    // 53568 : x,y,z,r tiles (4*128)
#define SH_WOUT   (SH_XYZR + 512)     // 54080 : W_out (64*3)
#define SH_BOUT   (SH_WOUT + 192)     // 54272 : b_out (3)
#define SH_TOTAL  (SH_BOUT + 4)       // 54276 floats
#define SMEM_BYTES (SH_TOTAL * 4)     // 217104 B

// ---------------- activations (match JAX semantics) ----------------
__device__ __forceinline__ float f_tanh(float v)     { return tanhf(v); }
__device__ __forceinline__ float f_elu(float v)      { return v > 0.f ? v : expm1f(v); }
__device__ __forceinline__ float f_softplus(float v) { return fmaxf(v, 0.f) + log1pf(expf(-fabsf(v))); }
__device__ __forceinline__ float f_sin(float v)      { return sinf(v); }
__device__ __forceinline__ float f_gauss(float v)    { return expf(-0.5f * v * v); }
__device__ __forceinline__ float f_sigmoid(float v)  { return 1.f / (1.f + expf(-v)); }

template <int ACT>
__device__ __forceinline__ float act_t(float v) {
    if (ACT == 0) return f_tanh(v);
    if (ACT == 1) return f_elu(v);
    if (ACT == 2) return f_softplus(v);
    if (ACT == 3) return f_sin(v);
    if (ACT == 4) return f_gauss(v);
    return f_sigmoid(v);
}

// stage a 64x64 weight matrix + 64 bias into shared
__device__ __forceinline__ void load_w(float* sh, const float* __restrict__ gW,
                                       const float* __restrict__ gb, int tid) {
#pragma unroll
    for (int i = 0; i < 4; i++) {
        int off = (tid + i * NTHREADS) * 4;
        *(float4*)(sh + SH_W + off) = *(const float4*)(gW + off);
    }
    if (tid < 16) ((float4*)(sh + SH_B))[tid] = ((const float4*)gb)[tid];
}

// ---------------- generic fused stage: D = ACT((A0[+A1[+A2]]) @ W + b) ----------------
// A/D are [128][64] row-major tiles in shared. Each thread owns an 8x4 C tile.
template <int NP, int ACT>
__device__ __forceinline__ void mm_stage(float* sh, int s0, int s1, int s2,
                                         int dst, int m0, int n0) {
    const float* A0 = sh + s0 * HBUF;
    const float* A1 = sh + s1 * HBUF;
    const float* A2 = sh + s2 * HBUF;
    const float* W  = sh + SH_W;
    float* D        = sh + dst * HBUF;

    float4 bb = *(const float4*)(sh + SH_B + n0);
    float acc[8][4];
#pragma unroll
    for (int i = 0; i < 8; i++) {
        acc[i][0] = bb.x; acc[i][1] = bb.y; acc[i][2] = bb.z; acc[i][3] = bb.w;
    }

#pragma unroll 4
    for (int k0 = 0; k0 < 64; k0 += 4) {
        float4 a[8];
#pragma unroll
        for (int i = 0; i < 8; i++) {
            float4 v = *(const float4*)(A0 + (m0 + i) * 64 + k0);
            if (NP > 1) {
                float4 u = *(const float4*)(A1 + (m0 + i) * 64 + k0);
                v.x += u.x; v.y += u.y; v.z += u.z; v.w += u.w;
            }
            if (NP > 2) {
                float4 u = *(const float4*)(A2 + (m0 + i) * 64 + k0);
                v.x += u.x; v.y += u.y; v.z += u.z; v.w += u.w;
            }
            a[i] = v;
        }
        float4 w0 = *(const float4*)(W + (k0 + 0) * 64 + n0);
        float4 w1 = *(const float4*)(W + (k0 + 1) * 64 + n0);
        float4 w2 = *(const float4*)(W + (k0 + 2) * 64 + n0);
        float4 w3 = *(const float4*)(W + (k0 + 3) * 64 + n0);
#pragma unroll
        for (int i = 0; i < 8; i++) {
            acc[i][0] = fmaf(a[i].x, w0.x, acc[i][0]);
            acc[i][1] = fmaf(a[i].x, w0.y, acc[i][1]);
            acc[i][2] = fmaf(a[i].x, w0.z, acc[i][2]);
            acc[i][3] = fmaf(a[i].x, w0.w, acc[i][3]);
            acc[i][0] = fmaf(a[i].y, w1.x, acc[i][0]);
            acc[i][1] = fmaf(a[i].y, w1.y, acc[i][1]);
            acc[i][2] = fmaf(a[i].y, w1.z, acc[i][2]);
            acc[i][3] = fmaf(a[i].y, w1.w, acc[i][3]);
            acc[i][0] = fmaf(a[i].z, w2.x, acc[i][0]);
            acc[i][1] = fmaf(a[i].z, w2.y, acc[i][1]);
            acc[i][2] = fmaf(a[i].z, w2.z, acc[i][2]);
            acc[i][3] = fmaf(a[i].z, w2.w, acc[i][3]);
            acc[i][0] = fmaf(a[i].w, w3.x, acc[i][0]);
            acc[i][1] = fmaf(a[i].w, w3.y, acc[i][1]);
            acc[i][2] = fmaf(a[i].w, w3.z, acc[i][2]);
            acc[i][3] = fmaf(a[i].w, w3.w, acc[i][3]);
        }
    }

#pragma unroll
    for (int i = 0; i < 8; i++) {
        float4 o;
        o.x = act_t<ACT>(acc[i][0]);
        o.y = act_t<ACT>(acc[i][1]);
        o.z = act_t<ACT>(acc[i][2]);
        o.w = act_t<ACT>(acc[i][3]);
        *(float4*)(D + (m0 + i) * 64 + n0) = o;
    }
}

// ---------------- input stage: S_in = sin(elu+gauss+tanh+softplus branches + tanh(noise@Wn+bn)) ----------------
// noise tile staged in buffer 2 as [128][16]; result written to buffer 1.
__device__ __forceinline__ void pre_stage(float* sh, int m0, int n0) {
    const float* A  = sh + 2 * HBUF;   // noise [128][16]
    const float* W  = sh + SH_W;       // W_noise [16][64]
    const float* Bn = sh + SH_B;
    float* D        = sh + 1 * HBUF;

    float acc[8][4];
#pragma unroll
    for (int i = 0; i < 8; i++) { acc[i][0] = 0.f; acc[i][1] = 0.f; acc[i][2] = 0.f; acc[i][3] = 0.f; }

#pragma unroll
    for (int k0 = 0; k0 < 16; k0 += 4) {
        float4 a[8];
#pragma unroll
        for (int i = 0; i < 8; i++)
            a[i] = *(const float4*)(A + (m0 + i) * 16 + k0);
        float4 w0 = *(const float4*)(W + (k0 + 0) * 64 + n0);
        float4 w1 = *(const float4*)(W + (k0 + 1) * 64 + n0);
        float4 w2 = *(const float4*)(W + (k0 + 2) * 64 + n0);
        float4 w3 = *(const float4*)(W + (k0 + 3) * 64 + n0);
#pragma unroll
        for (int i = 0; i < 8; i++) {
            acc[i][0] = fmaf(a[i].x, w0.x, acc[i][0]);
            acc[i][1] = fmaf(a[i].x, w0.y, acc[i][1]);
            acc[i][2] = fmaf(a[i].x, w0.z, acc[i][2]);
            acc[i][3] = fmaf(a[i].x, w0.w, acc[i][3]);
            acc[i][0] = fmaf(a[i].y, w1.x, acc[i][0]);
            acc[i][1] = fmaf(a[i].y, w1.y, acc[i][1]);
            acc[i][2] = fmaf(a[i].y, w1.z, acc[i][2]);
            acc[i][3] = fmaf(a[i].y, w1.w, acc[i][3]);
            acc[i][0] = fmaf(a[i].z, w2.x, acc[i][0]);
            acc[i][1] = fmaf(a[i].z, w2.y, acc[i][1]);
            acc[i][2] = fmaf(a[i].z, w2.z, acc[i][2]);
            acc[i][3] = fmaf(a[i].z, w2.w, acc[i][3]);
            acc[i][0] = fmaf(a[i].w, w3.x, acc[i][0]);
            acc[i][1] = fmaf(a[i].w, w3.y, acc[i][1]);
            acc[i][2] = fmaf(a[i].w, w3.z, acc[i][2]);
            acc[i][3] = fmaf(a[i].w, w3.w, acc[i][3]);
        }
    }

    const float* xs = sh + SH_XYZR;
#pragma unroll
    for (int i = 0; i < 8; i++) {
        int m = m0 + i;
        float xm = xs[m], ym = xs[128 + m], zm = xs[256 + m], rm = xs[384 + m];
        float vals[4];
#pragma unroll
        for (int j = 0; j < 4; j++) {
            int nn = n0 + j;
            float nd = f_tanh(acc[i][j] + Bn[nn]);
            float zb = f_elu(zm * sh[SH_WXYZR + 128 + nn]);
            float xb = f_gauss(xm * sh[SH_WXYZR + nn]);
            float yb = f_tanh(ym * sh[SH_WXYZR + 64 + nn]);
            float rb = f_softplus(rm * sh[SH_WXYZR + 192 + nn]);
            vals[j] = f_sin(zb + xb + yb + rb + nd);
        }
        float4 o = {vals[0], vals[1], vals[2], vals[3]};
        *(float4*)(D + m * 64 + n0) = o;
    }
}

// ---------------- main kernel: full network for a 128-point tile ----------------
__global__ __launch_bounds__(NTHREADS) void inr_kernel(
    const float* __restrict__ x, const float* __restrict__ y,
    const float* __restrict__ z, const float* __restrict__ r,
    const float* __restrict__ noise,
    const float* __restrict__ Wn, const float* __restrict__ bn,
    const float* __restrict__ Wx, const float* __restrict__ Wy,
    const float* __restrict__ Wz, const float* __restrict__ Wr,
    const float* __restrict__ W1, const float* __restrict__ b1,
    const float* __restrict__ Wg, const float* __restrict__ bg,
    const float* __restrict__ Wout, const float* __restrict__ bout,
    float* __restrict__ out)
{
    extern __shared__ float sh[];
    const int tid = threadIdx.x;
    const int tm = tid >> 4, tn = tid & 15;
    const int m0 = tm * 8, n0 = tn * 4;
    const long base = (long)blockIdx.x * TILE_M;

    // ---- stage inputs ----
    {
        const float4* src = (const float4*)(noise + base * 16);
        float4* dst = (float4*)(sh + 2 * HBUF);   // noise tile -> buffer 2 (free now)
#pragma unroll
        for (int i = tid; i < TILE_M * 16 / 4; i += NTHREADS) dst[i] = src[i];
    }
    if (tid < TILE_M) {
        sh[SH_XYZR + 0   + tid] = x[base + tid];
        sh[SH_XYZR + 128 + tid] = y[base + tid];
        sh[SH_XYZR + 256 + tid] = z[base + tid];
        sh[SH_XYZR + 384 + tid] = r[base + tid];
    }
    if (tid < 64) {
        sh[SH_WXYZR + tid]       = Wx[tid];
        sh[SH_WXYZR + 64  + tid] = Wy[tid];
        sh[SH_WXYZR + 128 + tid] = Wz[tid];
        sh[SH_WXYZR + 192 + tid] = Wr[tid];
    }
    if (tid < 48) ((float4*)(sh + SH_WOUT))[tid] = ((const float4*)Wout)[tid];
    if (tid == 0) { sh[SH_BOUT] = bout[0]; sh[SH_BOUT + 1] = bout[1]; sh[SH_BOUT + 2] = bout[2]; }
    // W_noise (16x64) + b_noise
    for (int i = tid * 4; i < 16 * 64; i += NTHREADS * 4)
        *(float4*)(sh + SH_W + i) = *(const float4*)(Wn + i);
    if (tid < 16) ((float4*)(sh + SH_B))[tid] = ((const float4*)bn)[tid];
    __syncthreads();

    // ---- input branches + noise linear -> S_in in buffer 1 ----
    pre_stage(sh, m0, n0);
    __syncthreads();

    // ---- f = tanh(S_in @ W1 + b1) -> buffer 0 (h0) ----
    load_w(sh, W1, b1, tid); __syncthreads();
    mm_stage<1, 0>(sh, 1, 0, 0, /*dst*/0, m0, n0); __syncthreads();

    // ---- 11 graph nodes (buffers via liveness: h0..h11 -> B{0,1,2,3,4,5,1,2,3,4,0,5}) ----
    load_w(sh, Wg + 0 * 4096, bg + 0 * 64, tid); __syncthreads();
    mm_stage<1, 0>(sh, 0, 0, 0, 1, m0, n0); __syncthreads();   // n0: tanh(h0)      -> h1
    load_w(sh, Wg + 1 * 4096, bg + 1 * 64, tid); __syncthreads();
    mm_stage<1, 1>(sh, 1, 0, 0, 2, m0, n0); __syncthreads();   // n1: elu(h1)       -> h2
    load_w(sh, Wg + 2 * 4096, bg + 2 * 64, tid); __syncthreads();
    mm_stage<2, 2>(sh, 2, 0, 0, 3, m0, n0); __syncthreads();   // n2: sp(h2+h0)     -> h3
    load_w(sh, Wg + 3 * 4096, bg + 3 * 64, tid); __syncthreads();
    mm_stage<3, 3>(sh, 3, 1, 0, 4, m0, n0); __syncthreads();   // n3: sin(h3+h1+h0) -> h4
    load_w(sh, Wg + 4 * 4096, bg + 4 * 64, tid); __syncthreads();
    mm_stage<2, 4>(sh, 4, 2, 0, 5, m0, n0); __syncthreads();   // n4: gauss(h4+h2)  -> h5
    load_w(sh, Wg + 5 * 4096, bg + 5 * 64, tid); __syncthreads();
    mm_stage<2, 5>(sh, 5, 3, 0, 1, m0, n0); __syncthreads();   // n5: sig(h5+h3)    -> h6
    load_w(sh, Wg + 6 * 4096, bg + 6 * 64, tid); __syncthreads();
    mm_stage<2, 0>(sh, 1, 4, 0, 2, m0, n0); __syncthreads();   // n6: tanh(h6+h4)   -> h7
    load_w(sh, Wg + 7 * 4096, bg + 7 * 64, tid); __syncthreads();
    mm_stage<3, 1>(sh, 2, 5, 0, 3, m0, n0); __syncthreads();   // n7: elu(h7+h5+h0) -> h8
    load_w(sh, Wg + 8 * 4096, bg + 8 * 64, tid); __syncthreads();
    mm_stage<2, 2>(sh, 3, 1, 0, 4, m0, n0); __syncthreads();   // n8: sp(h8+h6)     -> h9
    load_w(sh, Wg + 9 * 4096, bg + 9 * 64, tid); __syncthreads();
    mm_stage<2, 3>(sh, 4, 2, 0, 0, m0, n0); __syncthreads();   // n9: sin(h9+h7)    -> h10
    load_w(sh, Wg + 10 * 4096, bg + 10 * 64, tid); __syncthreads();
    mm_stage<2, 4>(sh, 0, 3, 0, 5, m0, n0); __syncthreads();   // n10: gauss(h10+h8)-> h11

    // ---- output: sigmoid(h11 @ W_out + b_out) ----
    if (tid < TILE_M) {
        const float* h  = sh + 5 * HBUF + tid * 64;
        const float* Wo = sh + SH_WOUT;
        float a0 = sh[SH_BOUT], a1 = sh[SH_BOUT + 1], a2 = sh[SH_BOUT + 2];
#pragma unroll
        for (int k = 0; k < 64; k++) {
            float hv = h[k];
            a0 = fmaf(hv, Wo[k * 3 + 0], a0);
            a1 = fmaf(hv, Wo[k * 3 + 1], a1);
            a2 = fmaf(hv, Wo[k * 3 + 2], a2);
        }
        long o = (base + tid) * 3;
        out[o + 0] = f_sigmoid(a0);
        out[o + 1] = f_sigmoid(a1);
        out[o + 2] = f_sigmoid(a2);
    }
}

extern "C" void kernel_launch(void* const* d_in, const int* in_sizes, int n_in,
                              void* d_out, int out_size) {
    const float* x     = (const float*)d_in[0];
    const float* y     = (const float*)d_in[1];
    const float* z     = (const float*)d_in[2];
    const float* r     = (const float*)d_in[3];
    const float* noise = (const float*)d_in[4];
    const float* Wn    = (const float*)d_in[5];
    const float* bn    = (const float*)d_in[6];
    const float* Wx    = (const float*)d_in[7];
    const float* Wy    = (const float*)d_in[8];
    const float* Wz    = (const float*)d_in[9];
    const float* Wr    = (const float*)d_in[10];
    const float* W1    = (const float*)d_in[11];
    const float* b1    = (const float*)d_in[12];
    const float* Wg    = (const float*)d_in[13];
    const float* bg    = (const float*)d_in[14];
    const float* Wout  = (const float*)d_in[15];
    const float* bout  = (const float*)d_in[16];

    int n = in_sizes[0];
    int grid = n / TILE_M;

    cudaFuncSetAttribute(inr_kernel, cudaFuncAttributeMaxDynamicSharedMemorySize, SMEM_BYTES);
    inr_kernel<<<grid, NTHREADS, SMEM_BYTES>>>(x, y, z, r, noise, Wn, bn, Wx, Wy, Wz, Wr,
                                               W1, b1, Wg, bg, Wout, bout, (float*)d_out);
}

// round 7
// speedup vs baseline: 1.0029x; 1.0029x over previous
#include <cuda_runtime.h>
#include <math.h>

#define TILE_M   128
#define NTHREADS 256
#define HBUF     (TILE_M * 64)

// shared memory layout (float offsets)
#define SH_W      (6 * HBUF)          // 49152 : staged weight matrix (<=64x64)
#define SH_B      (SH_W + 64 * 64)    // 53248 : staged bias (64)
#define SH_WXYZR  (SH_B + 64)         // 53312 : Wx,Wy,Wz,Wr (4*64)
#define SH_XYZR   (SH_WXYZR + 256)    // 53568 : x,y,z,r tiles (4*128)
#define SH_WOUT   (SH_XYZR + 512)     // 54080 : W_out (64*3)
#define SH_BOUT   (SH_WOUT + 192)     // 54272 : b_out (3)
#define SH_TOTAL  (SH_BOUT + 4)       // 54276 floats
#define SMEM_BYTES (SH_TOTAL * 4)     // 217104 B

// ---------------- activations (match JAX semantics) ----------------
__device__ __forceinline__ float f_tanh(float v)     { return tanhf(v); }
__device__ __forceinline__ float f_elu(float v)      { return v > 0.f ? v : expm1f(v); }
__device__ __forceinline__ float f_softplus(float v) { return fmaxf(v, 0.f) + log1pf(expf(-fabsf(v))); }
__device__ __forceinline__ float f_sin(float v)      { return sinf(v); }
__device__ __forceinline__ float f_gauss(float v)    { return expf(-0.5f * v * v); }
__device__ __forceinline__ float f_sigmoid(float v)  { return 1.f / (1.f + expf(-v)); }

template <int ACT>
__device__ __forceinline__ float act_t(float v) {
    if (ACT == 0) return f_tanh(v);
    if (ACT == 1) return f_elu(v);
    if (ACT == 2) return f_softplus(v);
    if (ACT == 3) return f_sin(v);
    if (ACT == 4) return f_gauss(v);
    return f_sigmoid(v);
}

// stage a 64x64 weight matrix + 64 bias into shared
__device__ __forceinline__ void load_w(float* sh, const float* __restrict__ gW,
                                       const float* __restrict__ gb, int tid) {
#pragma unroll
    for (int i = 0; i < 4; i++) {
        int off = (tid + i * NTHREADS) * 4;
        *(float4*)(sh + SH_W + off) = *(const float4*)(gW + off);
    }
    if (tid < 16) ((float4*)(sh + SH_B))[tid] = ((const float4*)gb)[tid];
}

// ---------------- generic fused stage: D = ACT((A0[+A1[+A2]]) @ W + b) ----------------
// A/D are [128][64] row-major tiles in shared. Each thread owns an 8x4 C tile.
template <int NP, int ACT>
__device__ __forceinline__ void mm_stage(float* sh, int s0, int s1, int s2,
                                         int dst, int m0, int n0) {
    const float* A0 = sh + s0 * HBUF;
    const float* A1 = sh + s1 * HBUF;
    const float* A2 = sh + s2 * HBUF;
    const float* W  = sh + SH_W;
    float* D        = sh + dst * HBUF;

    float4 bb = *(const float4*)(sh + SH_B + n0);
    float acc[8][4];
#pragma unroll
    for (int i = 0; i < 8; i++) {
        acc[i][0] = bb.x; acc[i][1] = bb.y; acc[i][2] = bb.z; acc[i][3] = bb.w;
    }

#pragma unroll 4
    for (int k0 = 0; k0 < 64; k0 += 4) {
        float4 a[8];
#pragma unroll
        for (int i = 0; i < 8; i++) {
            float4 v = *(const float4*)(A0 + (m0 + i) * 64 + k0);
            if (NP > 1) {
                float4 u = *(const float4*)(A1 + (m0 + i) * 64 + k0);
                v.x += u.x; v.y += u.y; v.z += u.z; v.w += u.w;
            }
            if (NP > 2) {
                float4 u = *(const float4*)(A2 + (m0 + i) * 64 + k0);
                v.x += u.x; v.y += u.y; v.z += u.z; v.w += u.w;
            }
            a[i] = v;
        }
        float4 w0 = *(const float4*)(W + (k0 + 0) * 64 + n0);
        float4 w1 = *(const float4*)(W + (k0 + 1) * 64 + n0);
        float4 w2 = *(const float4*)(W + (k0 + 2) * 64 + n0);
        float4 w3 = *(const float4*)(W + (k0 + 3) * 64 + n0);
#pragma unroll
        for (int i = 0; i < 8; i++) {
            acc[i][0] = fmaf(a[i].x, w0.x, acc[i][0]);
            acc[i][1] = fmaf(a[i].x, w0.y, acc[i][1]);
            acc[i][2] = fmaf(a[i].x, w0.z, acc[i][2]);
            acc[i][3] = fmaf(a[i].x, w0.w, acc[i][3]);
            acc[i][0] = fmaf(a[i].y, w1.x, acc[i][0]);
            acc[i][1] = fmaf(a[i].y, w1.y, acc[i][1]);
            acc[i][2] = fmaf(a[i].y, w1.z, acc[i][2]);
            acc[i][3] = fmaf(a[i].y, w1.w, acc[i][3]);
            acc[i][0] = fmaf(a[i].z, w2.x, acc[i][0]);
            acc[i][1] = fmaf(a[i].z, w2.y, acc[i][1]);
            acc[i][2] = fmaf(a[i].z, w2.z, acc[i][2]);
            acc[i][3] = fmaf(a[i].z, w2.w, acc[i][3]);
            acc[i][0] = fmaf(a[i].w, w3.x, acc[i][0]);
            acc[i][1] = fmaf(a[i].w, w3.y, acc[i][1]);
            acc[i][2] = fmaf(a[i].w, w3.z, acc[i][2]);
            acc[i][3] = fmaf(a[i].w, w3.w, acc[i][3]);
        }
    }

#pragma unroll
    for (int i = 0; i < 8; i++) {
        float4 o;
        o.x = act_t<ACT>(acc[i][0]);
        o.y = act_t<ACT>(acc[i][1]);
        o.z = act_t<ACT>(acc[i][2]);
        o.w = act_t<ACT>(acc[i][3]);
        *(float4*)(D + (m0 + i) * 64 + n0) = o;
    }
}

// ---------------- input stage: S_in = sin(elu+gauss+tanh+softplus branches + tanh(noise@Wn+bn)) ----------------
// noise tile staged in buffer 2 as [128][16]; result written to buffer 1.
__device__ __forceinline__ void pre_stage(float* sh, int m0, int n0) {
    const float* A  = sh + 2 * HBUF;   // noise [128][16]
    const float* W  = sh + SH_W;       // W_noise [16][64]
    const float* Bn = sh + SH_B;
    float* D        = sh + 1 * HBUF;

    float acc[8][4];
#pragma unroll
    for (int i = 0; i < 8; i++) { acc[i][0] = 0.f; acc[i][1] = 0.f; acc[i][2] = 0.f; acc[i][3] = 0.f; }

#pragma unroll
    for (int k0 = 0; k0 < 16; k0 += 4) {
        float4 a[8];
#pragma unroll
        for (int i = 0; i < 8; i++)
            a[i] = *(const float4*)(A + (m0 + i) * 16 + k0);
        float4 w0 = *(const float4*)(W + (k0 + 0) * 64 + n0);
        float4 w1 = *(const float4*)(W + (k0 + 1) * 64 + n0);
        float4 w2 = *(const float4*)(W + (k0 + 2) * 64 + n0);
        float4 w3 = *(const float4*)(W + (k0 + 3) * 64 + n0);
#pragma unroll
        for (int i = 0; i < 8; i++) {
            acc[i][0] = fmaf(a[i].x, w0.x, acc[i][0]);
            acc[i][1] = fmaf(a[i].x, w0.y, acc[i][1]);
            acc[i][2] = fmaf(a[i].x, w0.z, acc[i][2]);
            acc[i][3] = fmaf(a[i].x, w0.w, acc[i][3]);
            acc[i][0] = fmaf(a[i].y, w1.x, acc[i][0]);
            acc[i][1] = fmaf(a[i].y, w1.y, acc[i][1]);
            acc[i][2] = fmaf(a[i].y, w1.z, acc[i][2]);
            acc[i][3] = fmaf(a[i].y, w1.w, acc[i][3]);
            acc[i][0] = fmaf(a[i].z, w2.x, acc[i][0]);
            acc[i][1] = fmaf(a[i].z, w2.y, acc[i][1]);
            acc[i][2] = fmaf(a[i].z, w2.z, acc[i][2]);
            acc[i][3] = fmaf(a[i].z, w2.w, acc[i][3]);
            acc[i][0] = fmaf(a[i].w, w3.x, acc[i][0]);
            acc[i][1] = fmaf(a[i].w, w3.y, acc[i][1]);
            acc[i][2] = fmaf(a[i].w, w3.z, acc[i][2]);
            acc[i][3] = fmaf(a[i].w, w3.w, acc[i][3]);
        }
    }

    const float* xs = sh + SH_XYZR;
#pragma unroll
    for (int i = 0; i < 8; i++) {
        int m = m0 + i;
        float xm = xs[m], ym = xs[128 + m], zm = xs[256 + m], rm = xs[384 + m];
        float vals[4];
#pragma unroll
        for (int j = 0; j < 4; j++) {
            int nn = n0 + j;
            float nd = f_tanh(acc[i][j] + Bn[nn]);
            float zb = f_elu(zm * sh[SH_WXYZR + 128 + nn]);
            float xb = f_gauss(xm * sh[SH_WXYZR + nn]);
            float yb = f_tanh(ym * sh[SH_WXYZR + 64 + nn]);
            float rb = f_softplus(rm * sh[SH_WXYZR + 192 + nn]);
            vals[j] = f_sin(zb + xb + yb + rb + nd);
        }
        float4 o = {vals[0], vals[1], vals[2], vals[3]};
        *(float4*)(D + m * 64 + n0) = o;
    }
}

// ---------------- main kernel: full network for a 128-point tile ----------------
__global__ __launch_bounds__(NTHREADS) void inr_kernel(
    const float* __restrict__ x, const float* __restrict__ y,
    const float* __restrict__ z, const float* __restrict__ r,
    const float* __restrict__ noise,
    const float* __restrict__ Wn, const float* __restrict__ bn,
    const float* __restrict__ Wx, const float* __restrict__ Wy,
    const float* __restrict__ Wz, const float* __restrict__ Wr,
    const float* __restrict__ W1, const float* __restrict__ b1,
    const float* __restrict__ Wg, const float* __restrict__ bg,
    const float* __restrict__ Wout, const float* __restrict__ bout,
    float* __restrict__ out)
{
    extern __shared__ float sh[];
    const int tid = threadIdx.x;
    const int tm = tid >> 4, tn = tid & 15;
    const int m0 = tm * 8, n0 = tn * 4;
    const long base = (long)blockIdx.x * TILE_M;

    // ---- stage inputs ----
    {
        const float4* src = (const float4*)(noise + base * 16);
        float4* dst = (float4*)(sh + 2 * HBUF);   // noise tile -> buffer 2 (free now)
#pragma unroll
        for (int i = tid; i < TILE_M * 16 / 4; i += NTHREADS) dst[i] = src[i];
    }
    if (tid < TILE_M) {
        sh[SH_XYZR + 0   + tid] = x[base + tid];
        sh[SH_XYZR + 128 + tid] = y[base + tid];
        sh[SH_XYZR + 256 + tid] = z[base + tid];
        sh[SH_XYZR + 384 + tid] = r[base + tid];
    }
    if (tid < 64) {
        sh[SH_WXYZR + tid]       = Wx[tid];
        sh[SH_WXYZR + 64  + tid] = Wy[tid];
        sh[SH_WXYZR + 128 + tid] = Wz[tid];
        sh[SH_WXYZR + 192 + tid] = Wr[tid];
    }
    if (tid < 48) ((float4*)(sh + SH_WOUT))[tid] = ((const float4*)Wout)[tid];
    if (tid == 0) { sh[SH_BOUT] = bout[0]; sh[SH_BOUT + 1] = bout[1]; sh[SH_BOUT + 2] = bout[2]; }
    // W_noise (16x64) + b_noise
    for (int i = tid * 4; i < 16 * 64; i += NTHREADS * 4)
        *(float4*)(sh + SH_W + i) = *(const float4*)(Wn + i);
    if (tid < 16) ((float4*)(sh + SH_B))[tid] = ((const float4*)bn)[tid];
    __syncthreads();

    // ---- input branches + noise linear -> S_in in buffer 1 ----
    pre_stage(sh, m0, n0);
    __syncthreads();

    // ---- f = tanh(S_in @ W1 + b1) -> buffer 0 (h0) ----
    load_w(sh, W1, b1, tid); __syncthreads();
    mm_stage<1, 0>(sh, 1, 0, 0, /*dst*/0, m0, n0); __syncthreads();

    // ---- 11 graph nodes (buffers via liveness: h0..h11 -> B{0,1,2,3,4,5,1,2,3,4,0,5}) ----
    load_w(sh, Wg + 0 * 4096, bg + 0 * 64, tid); __syncthreads();
    mm_stage<1, 0>(sh, 0, 0, 0, 1, m0, n0); __syncthreads();   // n0: tanh(h0)      -> h1
    load_w(sh, Wg + 1 * 4096, bg + 1 * 64, tid); __syncthreads();
    mm_stage<1, 1>(sh, 1, 0, 0, 2, m0, n0); __syncthreads();   // n1: elu(h1)       -> h2
    load_w(sh, Wg + 2 * 4096, bg + 2 * 64, tid); __syncthreads();
    mm_stage<2, 2>(sh, 2, 0, 0, 3, m0, n0); __syncthreads();   // n2: sp(h2+h0)     -> h3
    load_w(sh, Wg + 3 * 4096, bg + 3 * 64, tid); __syncthreads();
    mm_stage<3, 3>(sh, 3, 1, 0, 4, m0, n0); __syncthreads();   // n3: sin(h3+h1+h0) -> h4
    load_w(sh, Wg + 4 * 4096, bg + 4 * 64, tid); __syncthreads();
    mm_stage<2, 4>(sh, 4, 2, 0, 5, m0, n0); __syncthreads();   // n4: gauss(h4+h2)  -> h5
    load_w(sh, Wg + 5 * 4096, bg + 5 * 64, tid); __syncthreads();
    mm_stage<2, 5>(sh, 5, 3, 0, 1, m0, n0); __syncthreads();   // n5: sig(h5+h3)    -> h6
    load_w(sh, Wg + 6 * 4096, bg + 6 * 64, tid); __syncthreads();
    mm_stage<2, 0>(sh, 1, 4, 0, 2, m0, n0); __syncthreads();   // n6: tanh(h6+h4)   -> h7
    load_w(sh, Wg + 7 * 4096, bg + 7 * 64, tid); __syncthreads();
    mm_stage<3, 1>(sh, 2, 5, 0, 3, m0, n0); __syncthreads();   // n7: elu(h7+h5+h0) -> h8
    load_w(sh, Wg + 8 * 4096, bg + 8 * 64, tid); __syncthreads();
    mm_stage<2, 2>(sh, 3, 1, 0, 4, m0, n0); __syncthreads();   // n8: sp(h8+h6)     -> h9
    load_w(sh, Wg + 9 * 4096, bg + 9 * 64, tid); __syncthreads();
    mm_stage<2, 3>(sh, 4, 2, 0, 0, m0, n0); __syncthreads();   // n9: sin(h9+h7)    -> h10
    load_w(sh, Wg + 10 * 4096, bg + 10 * 64, tid); __syncthreads();
    mm_stage<2, 4>(sh, 0, 3, 0, 5, m0, n0); __syncthreads();   // n10: gauss(h10+h8)-> h11

    // ---- output: sigmoid(h11 @ W_out + b_out) ----
    if (tid < TILE_M) {
        const float* h  = sh + 5 * HBUF + tid * 64;
        const float* Wo = sh + SH_WOUT;
        float a0 = sh[SH_BOUT], a1 = sh[SH_BOUT + 1], a2 = sh[SH_BOUT + 2];
#pragma unroll
        for (int k = 0; k < 64; k++) {
            float hv = h[k];
            a0 = fmaf(hv, Wo[k * 3 + 0], a0);
            a1 = fmaf(hv, Wo[k * 3 + 1], a1);
            a2 = fmaf(hv, Wo[k * 3 + 2], a2);
        }
        long o = (base + tid) * 3;
        out[o + 0] = f_sigmoid(a0);
        out[o + 1] = f_sigmoid(a1);
        out[o + 2] = f_sigmoid(a2);
    }
}

extern "C" void kernel_launch(void* const* d_in, const int* in_sizes, int n_in,
                              void* d_out, int out_size) {
    const float* x     = (const float*)d_in[0];
    const float* y     = (const float*)d_in[1];
    const float* z     = (const float*)d_in[2];
    const float* r     = (const float*)d_in[3];
    const float* noise = (const float*)d_in[4];
    const float* Wn    = (const float*)d_in[5];
    const float* bn    = (const float*)d_in[6];
    const float* Wx    = (const float*)d_in[7];
    const float* Wy    = (const float*)d_in[8];
    const float* Wz    = (const float*)d_in[9];
    const float* Wr    = (const float*)d_in[10];
    const float* W1    = (const float*)d_in[11];
    const float* b1    = (const float*)d_in[12];
    const float* Wg    = (const float*)d_in[13];
    const float* bg    = (const float*)d_in[14];
    const float* Wout  = (const float*)d_in[15];
    const float* bout  = (const float*)d_in[16];

    int n = in_sizes[0];
    int grid = n / TILE_M;

    cudaFuncSetAttribute(inr_kernel, cudaFuncAttributeMaxDynamicSharedMemorySize, SMEM_BYTES);
    inr_kernel<<<grid, NTHREADS, SMEM_BYTES>>>(x, y, z, r, noise, Wn, bn, Wx, Wy, Wz, Wr,
                                               W1, b1, Wg, bg, Wout, bout, (float*)d_out);
}

// round 10
// speedup vs baseline: 1.0035x; 1.0005x over previous
#include <cuda_runtime.h>
#include <math.h>

#define TILE_M   128
#define NTHREADS 256
#define HBUF     (TILE_M * 64)

// shared memory layout (float offsets)
#define SH_W      (6 * HBUF)          // 49152 : staged weight matrix (<=64x64)
#define SH_B      (SH_W + 64 * 64)    // 53248 : staged bias (64)
#define SH_WXYZR  (SH_B + 64)         // 53312 : Wx,Wy,Wz,Wr (4*64)
#define SH_XYZR   (SH_WXYZR + 256)    // 53568 : x,y,z,r tiles (4*128)
#define SH_WOUT   (SH_XYZR + 512)     // 54080 : W_out (64*3)
#define SH_BOUT   (SH_WOUT + 192)     // 54272 : b_out (3)
#define SH_TOTAL  (SH_BOUT + 4)       // 54276 floats
#define SMEM_BYTES (SH_TOTAL * 4)     // 217104 B

// ---------------- activations (match JAX semantics) ----------------
__device__ __forceinline__ float f_tanh(float v)     { return tanhf(v); }
__device__ __forceinline__ float f_elu(float v)      { return v > 0.f ? v : expm1f(v); }
__device__ __forceinline__ float f_softplus(float v) { return fmaxf(v, 0.f) + log1pf(expf(-fabsf(v))); }
__device__ __forceinline__ float f_sin(float v)      { return sinf(v); }
__device__ __forceinline__ float f_gauss(float v)    { return expf(-0.5f * v * v); }
__device__ __forceinline__ float f_sigmoid(float v)  { return 1.f / (1.f + expf(-v)); }

template <int ACT>
__device__ __forceinline__ float act_t(float v) {
    if (ACT == 0) return f_tanh(v);
    if (ACT == 1) return f_elu(v);
    if (ACT == 2) return f_softplus(v);
    if (ACT == 3) return f_sin(v);
    if (ACT == 4) return f_gauss(v);
    return f_sigmoid(v);
}

// stage a 64x64 weight matrix + 64 bias into shared
__device__ __forceinline__ void load_w(float* sh, const float* __restrict__ gW,
                                       const float* __restrict__ gb, int tid) {
#pragma unroll
    for (int i = 0; i < 4; i++) {
        int off = (tid + i * NTHREADS) * 4;
        *(float4*)(sh + SH_W + off) = *(const float4*)(gW + off);
    }
    if (tid < 16) ((float4*)(sh + SH_B))[tid] = ((const float4*)gb)[tid];
}

// ---------------- generic fused stage: D = ACT((A0[+A1[+A2]]) @ W + b) ----------------
// A/D are [128][64] row-major tiles in shared. Each thread owns an 8x4 C tile.
template <int NP, int ACT>
__device__ __forceinline__ void mm_stage(float* sh, int s0, int s1, int s2,
                                         int dst, int m0, int n0) {
    const float* A0 = sh + s0 * HBUF;
    const float* A1 = sh + s1 * HBUF;
    const float* A2 = sh + s2 * HBUF;
    const float* W  = sh + SH_W;
    float* D        = sh + dst * HBUF;

    float4 bb = *(const float4*)(sh + SH_B + n0);
    float acc[8][4];
#pragma unroll
    for (int i = 0; i < 8; i++) {
        acc[i][0] = bb.x; acc[i][1] = bb.y; acc[i][2] = bb.z; acc[i][3] = bb.w;
    }

#pragma unroll 4
    for (int k0 = 0; k0 < 64; k0 += 4) {
        float4 a[8];
#pragma unroll
        for (int i = 0; i < 8; i++) {
            float4 v = *(const float4*)(A0 + (m0 + i) * 64 + k0);
            if (NP > 1) {
                float4 u = *(const float4*)(A1 + (m0 + i) * 64 + k0);
                v.x += u.x; v.y += u.y; v.z += u.z; v.w += u.w;
            }
            if (NP > 2) {
                float4 u = *(const float4*)(A2 + (m0 + i) * 64 + k0);
                v.x += u.x; v.y += u.y; v.z += u.z; v.w += u.w;
            }
            a[i] = v;
        }
        float4 w0 = *(const float4*)(W + (k0 + 0) * 64 + n0);
        float4 w1 = *(const float4*)(W + (k0 + 1) * 64 + n0);
        float4 w2 = *(const float4*)(W + (k0 + 2) * 64 + n0);
        float4 w3 = *(const float4*)(W + (k0 + 3) * 64 + n0);
#pragma unroll
        for (int i = 0; i < 8; i++) {
            acc[i][0] = fmaf(a[i].x, w0.x, acc[i][0]);
            acc[i][1] = fmaf(a[i].x, w0.y, acc[i][1]);
            acc[i][2] = fmaf(a[i].x, w0.z, acc[i][2]);
            acc[i][3] = fmaf(a[i].x, w0.w, acc[i][3]);
            acc[i][0] = fmaf(a[i].y, w1.x, acc[i][0]);
            acc[i][1] = fmaf(a[i].y, w1.y, acc[i][1]);
            acc[i][2] = fmaf(a[i].y, w1.z, acc[i][2]);
            acc[i][3] = fmaf(a[i].y, w1.w, acc[i][3]);
            acc[i][0] = fmaf(a[i].z, w2.x, acc[i][0]);
            acc[i][1] = fmaf(a[i].z, w2.y, acc[i][1]);
            acc[i][2] = fmaf(a[i].z, w2.z, acc[i][2]);
            acc[i][3] = fmaf(a[i].z, w2.w, acc[i][3]);
            acc[i][0] = fmaf(a[i].w, w3.x, acc[i][0]);
            acc[i][1] = fmaf(a[i].w, w3.y, acc[i][1]);
            acc[i][2] = fmaf(a[i].w, w3.z, acc[i][2]);
            acc[i][3] = fmaf(a[i].w, w3.w, acc[i][3]);
        }
    }

#pragma unroll
    for (int i = 0; i < 8; i++) {
        float4 o;
        o.x = act_t<ACT>(acc[i][0]);
        o.y = act_t<ACT>(acc[i][1]);
        o.z = act_t<ACT>(acc[i][2]);
        o.w = act_t<ACT>(acc[i][3]);
        *(float4*)(D + (m0 + i) * 64 + n0) = o;
    }
}

// ---------------- input stage: S_in = sin(elu+gauss+tanh+softplus branches + tanh(noise@Wn+bn)) ----------------
// noise tile staged in buffer 2 as [128][16]; result written to buffer 1.
__device__ __forceinline__ void pre_stage(float* sh, int m0, int n0) {
    const float* A  = sh + 2 * HBUF;   // noise [128][16]
    const float* W  = sh + SH_W;       // W_noise [16][64]
    const float* Bn = sh + SH_B;
    float* D        = sh + 1 * HBUF;

    float acc[8][4];
#pragma unroll
    for (int i = 0; i < 8; i++) { acc[i][0] = 0.f; acc[i][1] = 0.f; acc[i][2] = 0.f; acc[i][3] = 0.f; }

#pragma unroll
    for (int k0 = 0; k0 < 16; k0 += 4) {
        float4 a[8];
#pragma unroll
        for (int i = 0; i < 8; i++)
            a[i] = *(const float4*)(A + (m0 + i) * 16 + k0);
        float4 w0 = *(const float4*)(W + (k0 + 0) * 64 + n0);
        float4 w1 = *(const float4*)(W + (k0 + 1) * 64 + n0);
        float4 w2 = *(const float4*)(W + (k0 + 2) * 64 + n0);
        float4 w3 = *(const float4*)(W + (k0 + 3) * 64 + n0);
#pragma unroll
        for (int i = 0; i < 8; i++) {
            acc[i][0] = fmaf(a[i].x, w0.x, acc[i][0]);
            acc[i][1] = fmaf(a[i].x, w0.y, acc[i][1]);
            acc[i][2] = fmaf(a[i].x, w0.z, acc[i][2]);
            acc[i][3] = fmaf(a[i].x, w0.w, acc[i][3]);
            acc[i][0] = fmaf(a[i].y, w1.x, acc[i][0]);
            acc[i][1] = fmaf(a[i].y, w1.y, acc[i][1]);
            acc[i][2] = fmaf(a[i].y, w1.z, acc[i][2]);
            acc[i][3] = fmaf(a[i].y, w1.w, acc[i][3]);
            acc[i][0] = fmaf(a[i].z, w2.x, acc[i][0]);
            acc[i][1] = fmaf(a[i].z, w2.y, acc[i][1]);
            acc[i][2] = fmaf(a[i].z, w2.z, acc[i][2]);
            acc[i][3] = fmaf(a[i].z, w2.w, acc[i][3]);
            acc[i][0] = fmaf(a[i].w, w3.x, acc[i][0]);
            acc[i][1] = fmaf(a[i].w, w3.y, acc[i][1]);
            acc[i][2] = fmaf(a[i].w, w3.z, acc[i][2]);
            acc[i][3] = fmaf(a[i].w, w3.w, acc[i][3]);
        }
    }

    const float* xs = sh + SH_XYZR;
#pragma unroll
    for (int i = 0; i < 8; i++) {
        int m = m0 + i;
        float xm = xs[m], ym = xs[128 + m], zm = xs[256 + m], rm = xs[384 + m];
        float vals[4];
#pragma unroll
        for (int j = 0; j < 4; j++) {
            int nn = n0 + j;
            float nd = f_tanh(acc[i][j] + Bn[nn]);
            float zb = f_elu(zm * sh[SH_WXYZR + 128 + nn]);
            float xb = f_gauss(xm * sh[SH_WXYZR + nn]);
            float yb = f_tanh(ym * sh[SH_WXYZR + 64 + nn]);
            float rb = f_softplus(rm * sh[SH_WXYZR + 192 + nn]);
            vals[j] = f_sin(zb + xb + yb + rb + nd);
        }
        float4 o = {vals[0], vals[1], vals[2], vals[3]};
        *(float4*)(D + m * 64 + n0) = o;
    }
}

// ---------------- main kernel: full network for a 128-point tile ----------------
__global__ __launch_bounds__(NTHREADS) void inr_kernel(
    const float* __restrict__ x, const float* __restrict__ y,
    const float* __restrict__ z, const float* __restrict__ r,
    const float* __restrict__ noise,
    const float* __restrict__ Wn, const float* __restrict__ bn,
    const float* __restrict__ Wx, const float* __restrict__ Wy,
    const float* __restrict__ Wz, const float* __restrict__ Wr,
    const float* __restrict__ W1, const float* __restrict__ b1,
    const float* __restrict__ Wg, const float* __restrict__ bg,
    const float* __restrict__ Wout, const float* __restrict__ bout,
    float* __restrict__ out)
{
    extern __shared__ float sh[];
    const int tid = threadIdx.x;
    const int tm = tid >> 4, tn = tid & 15;
    const int m0 = tm * 8, n0 = tn * 4;
    const long base = (long)blockIdx.x * TILE_M;

    // ---- stage inputs ----
    {
        const float4* src = (const float4*)(noise + base * 16);
        float4* dst = (float4*)(sh + 2 * HBUF);   // noise tile -> buffer 2 (free now)
#pragma unroll
        for (int i = tid; i < TILE_M * 16 / 4; i += NTHREADS) dst[i] = src[i];
    }
    if (tid < TILE_M) {
        sh[SH_XYZR + 0   + tid] = x[base + tid];
        sh[SH_XYZR + 128 + tid] = y[base + tid];
        sh[SH_XYZR + 256 + tid] = z[base + tid];
        sh[SH_XYZR + 384 + tid] = r[base + tid];
    }
    if (tid < 64) {
        sh[SH_WXYZR + tid]       = Wx[tid];
        sh[SH_WXYZR + 64  + tid] = Wy[tid];
        sh[SH_WXYZR + 128 + tid] = Wz[tid];
        sh[SH_WXYZR + 192 + tid] = Wr[tid];
    }
    if (tid < 48) ((float4*)(sh + SH_WOUT))[tid] = ((const float4*)Wout)[tid];
    if (tid == 0) { sh[SH_BOUT] = bout[0]; sh[SH_BOUT + 1] = bout[1]; sh[SH_BOUT + 2] = bout[2]; }
    // W_noise (16x64) + b_noise
    for (int i = tid * 4; i < 16 * 64; i += NTHREADS * 4)
        *(float4*)(sh + SH_W + i) = *(const float4*)(Wn + i);
    if (tid < 16) ((float4*)(sh + SH_B))[tid] = ((const float4*)bn)[tid];
    __syncthreads();

    // ---- input branches + noise linear -> S_in in buffer 1 ----
    pre_stage(sh, m0, n0);
    __syncthreads();

    // ---- f = tanh(S_in @ W1 + b1) -> buffer 0 (h0) ----
    load_w(sh, W1, b1, tid); __syncthreads();
    mm_stage<1, 0>(sh, 1, 0, 0, /*dst*/0, m0, n0); __syncthreads();

    // ---- 11 graph nodes (buffers via liveness: h0..h11 -> B{0,1,2,3,4,5,1,2,3,4,0,5}) ----
    load_w(sh, Wg + 0 * 4096, bg + 0 * 64, tid); __syncthreads();
    mm_stage<1, 0>(sh, 0, 0, 0, 1, m0, n0); __syncthreads();   // n0: tanh(h0)      -> h1
    load_w(sh, Wg + 1 * 4096, bg + 1 * 64, tid); __syncthreads();
    mm_stage<1, 1>(sh, 1, 0, 0, 2, m0, n0); __syncthreads();   // n1: elu(h1)       -> h2
    load_w(sh, Wg + 2 * 4096, bg + 2 * 64, tid); __syncthreads();
    mm_stage<2, 2>(sh, 2, 0, 0, 3, m0, n0); __syncthreads();   // n2: sp(h2+h0)     -> h3
    load_w(sh, Wg + 3 * 4096, bg + 3 * 64, tid); __syncthreads();
    mm_stage<3, 3>(sh, 3, 1, 0, 4, m0, n0); __syncthreads();   // n3: sin(h3+h1+h0) -> h4
    load_w(sh, Wg + 4 * 4096, bg + 4 * 64, tid); __syncthreads();
    mm_stage<2, 4>(sh, 4, 2, 0, 5, m0, n0); __syncthreads();   // n4: gauss(h4+h2)  -> h5
    load_w(sh, Wg + 5 * 4096, bg + 5 * 64, tid); __syncthreads();
    mm_stage<2, 5>(sh, 5, 3, 0, 1, m0, n0); __syncthreads();   // n5: sig(h5+h3)    -> h6
    load_w(sh, Wg + 6 * 4096, bg + 6 * 64, tid); __syncthreads();
    mm_stage<2, 0>(sh, 1, 4, 0, 2, m0, n0); __syncthreads();   // n6: tanh(h6+h4)   -> h7
    load_w(sh, Wg + 7 * 4096, bg + 7 * 64, tid); __syncthreads();
    mm_stage<3, 1>(sh, 2, 5, 0, 3, m0, n0); __syncthreads();   // n7: elu(h7+h5+h0) -> h8
    load_w(sh, Wg + 8 * 4096, bg + 8 * 64, tid); __syncthreads();
    mm_stage<2, 2>(sh, 3, 1, 0, 4, m0, n0); __syncthreads();   // n8: sp(h8+h6)     -> h9
    load_w(sh, Wg + 9 * 4096, bg + 9 * 64, tid); __syncthreads();
    mm_stage<2, 3>(sh, 4, 2, 0, 0, m0, n0); __syncthreads();   // n9: sin(h9+h7)    -> h10
    load_w(sh, Wg + 10 * 4096, bg + 10 * 64, tid); __syncthreads();
    mm_stage<2, 4>(sh, 0, 3, 0, 5, m0, n0); __syncthreads();   // n10: gauss(h10+h8)-> h11

    // ---- output: sigmoid(h11 @ W_out + b_out) ----
    if (tid < TILE_M) {
        const float* h  = sh + 5 * HBUF + tid * 64;
        const float* Wo = sh + SH_WOUT;
        float a0 = sh[SH_BOUT], a1 = sh[SH_BOUT + 1], a2 = sh[SH_BOUT + 2];
#pragma unroll
        for (int k = 0; k < 64; k++) {
            float hv = h[k];
            a0 = fmaf(hv, Wo[k * 3 + 0], a0);
            a1 = fmaf(hv, Wo[k * 3 + 1], a1);
            a2 = fmaf(hv, Wo[k * 3 + 2], a2);
        }
        long o = (base + tid) * 3;
        out[o + 0] = f_sigmoid(a0);
        out[o + 1] = f_sigmoid(a1);
        out[o + 2] = f_sigmoid(a2);
    }
}

extern "C" void kernel_launch(void* const* d_in, const int* in_sizes, int n_in,
                              void* d_out, int out_size) {
    const float* x     = (const float*)d_in[0];
    const float* y     = (const float*)d_in[1];
    const float* z     = (const float*)d_in[2];
    const float* r     = (const float*)d_in[3];
    const float* noise = (const float*)d_in[4];
    const float* Wn    = (const float*)d_in[5];
    const float* bn    = (const float*)d_in[6];
    const float* Wx    = (const float*)d_in[7];
    const float* Wy    = (const float*)d_in[8];
    const float* Wz    = (const float*)d_in[9];
    const float* Wr    = (const float*)d_in[10];
    const float* W1    = (const float*)d_in[11];
    const float* b1    = (const float*)d_in[12];
    const float* Wg    = (const float*)d_in[13];
    const float* bg    = (const float*)d_in[14];
    const float* Wout  = (const float*)d_in[15];
    const float* bout  = (const float*)d_in[16];

    int n = in_sizes[0];
    int grid = n / TILE_M;

    cudaFuncSetAttribute(inr_kernel, cudaFuncAttributeMaxDynamicSharedMemorySize, SMEM_BYTES);
    inr_kernel<<<grid, NTHREADS, SMEM_BYTES>>>(x, y, z, r, noise, Wn, bn, Wx, Wy, Wz, Wr,
                                               W1, b1, Wg, bg, Wout, bout, (float*)d_out);
}

// round 11
// speedup vs baseline: 1.0036x; 1.0002x over previous
#include <cuda_runtime.h>
#include <math.h>

#define TILE_M   128
#define NTHREADS 256
#define HBUF     (TILE_M * 64)

// shared memory layout (float offsets)
#define SH_W      (6 * HBUF)          // 49152 : staged weight matrix (<=64x64)
#define SH_B      (SH_W + 64 * 64)    // 53248 : staged bias (64)
#define SH_WXYZR  (SH_B + 64)         // 53312 : Wx,Wy,Wz,Wr (4*64)
#define SH_XYZR   (SH_WXYZR + 256)    // 53568 : x,y,z,r tiles (4*128)
#define SH_WOUT   (SH_XYZR + 512)     // 54080 : W_out (64*3)
#define SH_BOUT   (SH_WOUT + 192)     // 54272 : b_out (3)
#define SH_TOTAL  (SH_BOUT + 4)       // 54276 floats
#define SMEM_BYTES (SH_TOTAL * 4)     // 217104 B

// ---------------- activations (match JAX semantics) ----------------
__device__ __forceinline__ float f_tanh(float v)     { return tanhf(v); }
__device__ __forceinline__ float f_elu(float v)      { return v > 0.f ? v : expm1f(v); }
__device__ __forceinline__ float f_softplus(float v) { return fmaxf(v, 0.f) + log1pf(expf(-fabsf(v))); }
__device__ __forceinline__ float f_sin(float v)      { return sinf(v); }
__device__ __forceinline__ float f_gauss(float v)    { return expf(-0.5f * v * v); }
__device__ __forceinline__ float f_sigmoid(float v)  { return 1.f / (1.f + expf(-v)); }

template <int ACT>
__device__ __forceinline__ float act_t(float v) {
    if (ACT == 0) return f_tanh(v);
    if (ACT == 1) return f_elu(v);
    if (ACT == 2) return f_softplus(v);
    if (ACT == 3) return f_sin(v);
    if (ACT == 4) return f_gauss(v);
    return f_sigmoid(v);
}

// stage a 64x64 weight matrix + 64 bias into shared
__device__ __forceinline__ void load_w(float* sh, const float* __restrict__ gW,
                                       const float* __restrict__ gb, int tid) {
#pragma unroll
    for (int i = 0; i < 4; i++) {
        int off = (tid + i * NTHREADS) * 4;
        *(float4*)(sh + SH_W + off) = *(const float4*)(gW + off);
    }
    if (tid < 16) ((float4*)(sh + SH_B))[tid] = ((const float4*)gb)[tid];
}

// ---------------- generic fused stage: D = ACT((A0[+A1[+A2]]) @ W + b) ----------------
// A/D are [128][64] row-major tiles in shared. Each thread owns an 8x4 C tile.
template <int NP, int ACT>
__device__ __forceinline__ void mm_stage(float* sh, int s0, int s1, int s2,
                                         int dst, int m0, int n0) {
    const float* A0 = sh + s0 * HBUF;
    const float* A1 = sh + s1 * HBUF;
    const float* A2 = sh + s2 * HBUF;
    const float* W  = sh + SH_W;
    float* D        = sh + dst * HBUF;

    float4 bb = *(const float4*)(sh + SH_B + n0);
    float acc[8][4];
#pragma unroll
    for (int i = 0; i < 8; i++) {
        acc[i][0] = bb.x; acc[i][1] = bb.y; acc[i][2] = bb.z; acc[i][3] = bb.w;
    }

#pragma unroll 4
    for (int k0 = 0; k0 < 64; k0 += 4) {
        float4 a[8];
#pragma unroll
        for (int i = 0; i < 8; i++) {
            float4 v = *(const float4*)(A0 + (m0 + i) * 64 + k0);
            if (NP > 1) {
                float4 u = *(const float4*)(A1 + (m0 + i) * 64 + k0);
                v.x += u.x; v.y += u.y; v.z += u.z; v.w += u.w;
            }
            if (NP > 2) {
                float4 u = *(const float4*)(A2 + (m0 + i) * 64 + k0);
                v.x += u.x; v.y += u.y; v.z += u.z; v.w += u.w;
            }
            a[i] = v;
        }
        float4 w0 = *(const float4*)(W + (k0 + 0) * 64 + n0);
        float4 w1 = *(const float4*)(W + (k0 + 1) * 64 + n0);
        float4 w2 = *(const float4*)(W + (k0 + 2) * 64 + n0);
        float4 w3 = *(const float4*)(W + (k0 + 3) * 64 + n0);
#pragma unroll
        for (int i = 0; i < 8; i++) {
            acc[i][0] = fmaf(a[i].x, w0.x, acc[i][0]);
            acc[i][1] = fmaf(a[i].x, w0.y, acc[i][1]);
            acc[i][2] = fmaf(a[i].x, w0.z, acc[i][2]);
            acc[i][3] = fmaf(a[i].x, w0.w, acc[i][3]);
            acc[i][0] = fmaf(a[i].y, w1.x, acc[i][0]);
            acc[i][1] = fmaf(a[i].y, w1.y, acc[i][1]);
            acc[i][2] = fmaf(a[i].y, w1.z, acc[i][2]);
            acc[i][3] = fmaf(a[i].y, w1.w, acc[i][3]);
            acc[i][0] = fmaf(a[i].z, w2.x, acc[i][0]);
            acc[i][1] = fmaf(a[i].z, w2.y, acc[i][1]);
            acc[i][2] = fmaf(a[i].z, w2.z, acc[i][2]);
            acc[i][3] = fmaf(a[i].z, w2.w, acc[i][3]);
            acc[i][0] = fmaf(a[i].w, w3.x, acc[i][0]);
            acc[i][1] = fmaf(a[i].w, w3.y, acc[i][1]);
            acc[i][2] = fmaf(a[i].w, w3.z, acc[i][2]);
            acc[i][3] = fmaf(a[i].w, w3.w, acc[i][3]);
        }
    }

#pragma unroll
    for (int i = 0; i < 8; i++) {
        float4 o;
        o.x = act_t<ACT>(acc[i][0]);
        o.y = act_t<ACT>(acc[i][1]);
        o.z = act_t<ACT>(acc[i][2]);
        o.w = act_t<ACT>(acc[i][3]);
        *(float4*)(D + (m0 + i) * 64 + n0) = o;
    }
}

// ---------------- input stage: S_in = sin(elu+gauss+tanh+softplus branches + tanh(noise@Wn+bn)) ----------------
// noise tile staged in buffer 2 as [128][16]; result written to buffer 1.
__device__ __forceinline__ void pre_stage(float* sh, int m0, int n0) {
    const float* A  = sh + 2 * HBUF;   // noise [128][16]
    const float* W  = sh + SH_W;       // W_noise [16][64]
    const float* Bn = sh + SH_B;
    float* D        = sh + 1 * HBUF;

    float acc[8][4];
#pragma unroll
    for (int i = 0; i < 8; i++) { acc[i][0] = 0.f; acc[i][1] = 0.f; acc[i][2] = 0.f; acc[i][3] = 0.f; }

#pragma unroll
    for (int k0 = 0; k0 < 16; k0 += 4) {
        float4 a[8];
#pragma unroll
        for (int i = 0; i < 8; i++)
            a[i] = *(const float4*)(A + (m0 + i) * 16 + k0);
        float4 w0 = *(const float4*)(W + (k0 + 0) * 64 + n0);
        float4 w1 = *(const float4*)(W + (k0 + 1) * 64 + n0);
        float4 w2 = *(const float4*)(W + (k0 + 2) * 64 + n0);
        float4 w3 = *(const float4*)(W + (k0 + 3) * 64 + n0);
#pragma unroll
        for (int i = 0; i < 8; i++) {
            acc[i][0] = fmaf(a[i].x, w0.x, acc[i][0]);
            acc[i][1] = fmaf(a[i].x, w0.y, acc[i][1]);
            acc[i][2] = fmaf(a[i].x, w0.z, acc[i][2]);
            acc[i][3] = fmaf(a[i].x, w0.w, acc[i][3]);
            acc[i][0] = fmaf(a[i].y, w1.x, acc[i][0]);
            acc[i][1] = fmaf(a[i].y, w1.y, acc[i][1]);
            acc[i][2] = fmaf(a[i].y, w1.z, acc[i][2]);
            acc[i][3] = fmaf(a[i].y, w1.w, acc[i][3]);
            acc[i][0] = fmaf(a[i].z, w2.x, acc[i][0]);
            acc[i][1] = fmaf(a[i].z, w2.y, acc[i][1]);
            acc[i][2] = fmaf(a[i].z, w2.z, acc[i][2]);
            acc[i][3] = fmaf(a[i].z, w2.w, acc[i][3]);
            acc[i][0] = fmaf(a[i].w, w3.x, acc[i][0]);
            acc[i][1] = fmaf(a[i].w, w3.y, acc[i][1]);
            acc[i][2] = fmaf(a[i].w, w3.z, acc[i][2]);
            acc[i][3] = fmaf(a[i].w, w3.w, acc[i][3]);
        }
    }

    const float* xs = sh + SH_XYZR;
#pragma unroll
    for (int i = 0; i < 8; i++) {
        int m = m0 + i;
        float xm = xs[m], ym = xs[128 + m], zm = xs[256 + m], rm = xs[384 + m];
        float vals[4];
#pragma unroll
        for (int j = 0; j < 4; j++) {
            int nn = n0 + j;
            float nd = f_tanh(acc[i][j] + Bn[nn]);
            float zb = f_elu(zm * sh[SH_WXYZR + 128 + nn]);
            float xb = f_gauss(xm * sh[SH_WXYZR + nn]);
            float yb = f_tanh(ym * sh[SH_WXYZR + 64 + nn]);
            float rb = f_softplus(rm * sh[SH_WXYZR + 192 + nn]);
            vals[j] = f_sin(zb + xb + yb + rb + nd);
        }
        float4 o = {vals[0], vals[1], vals[2], vals[3]};
        *(float4*)(D + m * 64 + n0) = o;
    }
}

// ---------------- main kernel: full network for a 128-point tile ----------------
__global__ __launch_bounds__(NTHREADS) void inr_kernel(
    const float* __restrict__ x, const float* __restrict__ y,
    const float* __restrict__ z, const float* __restrict__ r,
    const float* __restrict__ noise,
    const float* __restrict__ Wn, const float* __restrict__ bn,
    const float* __restrict__ Wx, const float* __restrict__ Wy,
    const float* __restrict__ Wz, const float* __restrict__ Wr,
    const float* __restrict__ W1, const float* __restrict__ b1,
    const float* __restrict__ Wg, const float* __restrict__ bg,
    const float* __restrict__ Wout, const float* __restrict__ bout,
    float* __restrict__ out)
{
    extern __shared__ float sh[];
    const int tid = threadIdx.x;
    const int tm = tid >> 4, tn = tid & 15;
    const int m0 = tm * 8, n0 = tn * 4;
    const long base = (long)blockIdx.x * TILE_M;

    // ---- stage inputs ----
    {
        const float4* src = (const float4*)(noise + base * 16);
        float4* dst = (float4*)(sh + 2 * HBUF);   // noise tile -> buffer 2 (free now)
#pragma unroll
        for (int i = tid; i < TILE_M * 16 / 4; i += NTHREADS) dst[i] = src[i];
    }
    if (tid < TILE_M) {
        sh[SH_XYZR + 0   + tid] = x[base + tid];
        sh[SH_XYZR + 128 + tid] = y[base + tid];
        sh[SH_XYZR + 256 + tid] = z[base + tid];
        sh[SH_XYZR + 384 + tid] = r[base + tid];
    }
    if (tid < 64) {
        sh[SH_WXYZR + tid]       = Wx[tid];
        sh[SH_WXYZR + 64  + tid] = Wy[tid];
        sh[SH_WXYZR + 128 + tid] = Wz[tid];
        sh[SH_WXYZR + 192 + tid] = Wr[tid];
    }
    if (tid < 48) ((float4*)(sh + SH_WOUT))[tid] = ((const float4*)Wout)[tid];
    if (tid == 0) { sh[SH_BOUT] = bout[0]; sh[SH_BOUT + 1] = bout[1]; sh[SH_BOUT + 2] = bout[2]; }
    // W_noise (16x64) + b_noise
    for (int i = tid * 4; i < 16 * 64; i += NTHREADS * 4)
        *(float4*)(sh + SH_W + i) = *(const float4*)(Wn + i);
    if (tid < 16) ((float4*)(sh + SH_B))[tid] = ((const float4*)bn)[tid];
    __syncthreads();

    // ---- input branches + noise linear -> S_in in buffer 1 ----
    pre_stage(sh, m0, n0);
    __syncthreads();

    // ---- f = tanh(S_in @ W1 + b1) -> buffer 0 (h0) ----
    load_w(sh, W1, b1, tid); __syncthreads();
    mm_stage<1, 0>(sh, 1, 0, 0, /*dst*/0, m0, n0); __syncthreads();

    // ---- 11 graph nodes (buffers via liveness: h0..h11 -> B{0,1,2,3,4,5,1,2,3,4,0,5}) ----
    load_w(sh, Wg + 0 * 4096, bg + 0 * 64, tid); __syncthreads();
    mm_stage<1, 0>(sh, 0, 0, 0, 1, m0, n0); __syncthreads();   // n0: tanh(h0)      -> h1
    load_w(sh, Wg + 1 * 4096, bg + 1 * 64, tid); __syncthreads();
    mm_stage<1, 1>(sh, 1, 0, 0, 2, m0, n0); __syncthreads();   // n1: elu(h1)       -> h2
    load_w(sh, Wg + 2 * 4096, bg + 2 * 64, tid); __syncthreads();
    mm_stage<2, 2>(sh, 2, 0, 0, 3, m0, n0); __syncthreads();   // n2: sp(h2+h0)     -> h3
    load_w(sh, Wg + 3 * 4096, bg + 3 * 64, tid); __syncthreads();
    mm_stage<3, 3>(sh, 3, 1, 0, 4, m0, n0); __syncthreads();   // n3: sin(h3+h1+h0) -> h4
    load_w(sh, Wg + 4 * 4096, bg + 4 * 64, tid); __syncthreads();
    mm_stage<2, 4>(sh, 4, 2, 0, 5, m0, n0); __syncthreads();   // n4: gauss(h4+h2)  -> h5
    load_w(sh, Wg + 5 * 4096, bg + 5 * 64, tid); __syncthreads();
    mm_stage<2, 5>(sh, 5, 3, 0, 1, m0, n0); __syncthreads();   // n5: sig(h5+h3)    -> h6
    load_w(sh, Wg + 6 * 4096, bg + 6 * 64, tid); __syncthreads();
    mm_stage<2, 0>(sh, 1, 4, 0, 2, m0, n0); __syncthreads();   // n6: tanh(h6+h4)   -> h7
    load_w(sh, Wg + 7 * 4096, bg + 7 * 64, tid); __syncthreads();
    mm_stage<3, 1>(sh, 2, 5, 0, 3, m0, n0); __syncthreads();   // n7: elu(h7+h5+h0) -> h8
    load_w(sh, Wg + 8 * 4096, bg + 8 * 64, tid); __syncthreads();
    mm_stage<2, 2>(sh, 3, 1, 0, 4, m0, n0); __syncthreads();   // n8: sp(h8+h6)     -> h9
    load_w(sh, Wg + 9 * 4096, bg + 9 * 64, tid); __syncthreads();
    mm_stage<2, 3>(sh, 4, 2, 0, 0, m0, n0); __syncthreads();   // n9: sin(h9+h7)    -> h10
    load_w(sh, Wg + 10 * 4096, bg + 10 * 64, tid); __syncthreads();
    mm_stage<2, 4>(sh, 0, 3, 0, 5, m0, n0); __syncthreads();   // n10: gauss(h10+h8)-> h11

    // ---- output: sigmoid(h11 @ W_out + b_out) ----
    if (tid < TILE_M) {
        const float* h  = sh + 5 * HBUF + tid * 64;
        const float* Wo = sh + SH_WOUT;
        float a0 = sh[SH_BOUT], a1 = sh[SH_BOUT + 1], a2 = sh[SH_BOUT + 2];
#pragma unroll
        for (int k = 0; k < 64; k++) {
            float hv = h[k];
            a0 = fmaf(hv, Wo[k * 3 + 0], a0);
            a1 = fmaf(hv, Wo[k * 3 + 1], a1);
            a2 = fmaf(hv, Wo[k * 3 + 2], a2);
        }
        long o = (base + tid) * 3;
        out[o + 0] = f_sigmoid(a0);
        out[o + 1] = f_sigmoid(a1);
        out[o + 2] = f_sigmoid(a2);
    }
}

extern "C" void kernel_launch(void* const* d_in, const int* in_sizes, int n_in,
                              void* d_out, int out_size) {
    const float* x     = (const float*)d_in[0];
    const float* y     = (const float*)d_in[1];
    const float* z     = (const float*)d_in[2];
    const float* r     = (const float*)d_in[3];
    const float* noise = (const float*)d_in[4];
    const float* Wn    = (const float*)d_in[5];
    const float* bn    = (const float*)d_in[6];
    const float* Wx    = (const float*)d_in[7];
    const float* Wy    = (const float*)d_in[8];
    const float* Wz    = (const float*)d_in[9];
    const float* Wr    = (const float*)d_in[10];
    const float* W1    = (const float*)d_in[11];
    const float* b1    = (const float*)d_in[12];
    const float* Wg    = (const float*)d_in[13];
    const float* bg    = (const float*)d_in[14];
    const float* Wout  = (const float*)d_in[15];
    const float* bout  = (const float*)d_in[16];

    int n = in_sizes[0];
    int grid = n / TILE_M;

    cudaFuncSetAttribute(inr_kernel, cudaFuncAttributeMaxDynamicSharedMemorySize, SMEM_BYTES);
    inr_kernel<<<grid, NTHREADS, SMEM_BYTES>>>(x, y, z, r, noise, Wn, bn, Wx, Wy, Wz, Wr,
                                               W1, b1, Wg, bg, Wout, bout, (float*)d_out);
}